// round 13
// baseline (speedup 1.0000x reference)
#include <cuda_runtime.h>

#define CONST_NO 10000
#define PADV 0

constexpr int GG = 8;      // goals per state
constexpr int SS = 64;     // states per batch
constexpr int KF = 64;     // fact top-k
constexpr int KR = 32;     // rule top-k
constexpr int MAXSTATES = 512;
constexpr int MAXB = MAXSTATES / SS;
constexpr int NPREDS = 52;      // predicate ids 1..50 (+pad margin)
constexpr int SORT_BLK = 1024;
constexpr int SNW = SORT_BLK / 32;  // 32 warps
constexpr int NB_MAX = 256;
constexpr int MAXF = 200704;
constexpr int MT = 512;         // match threads per block
constexpr int MNW = MT / 32;    // match warps per block (16)
constexpr int HCH = 4;          // hist chunks per block
constexpr int SCH = 2;          // scatter chunks per block

__device__ int      g_hist[NPREDS * NB_MAX];  // [pred][chunk] counts
__device__ int      g_bucketCount[NPREDS];
__device__ int      g_bucketStart[NPREDS];
__device__ unsigned g_keys[MAXF];             // packed (a0 | a1<<14), bucketed, index-ordered
__device__ int      g_sIdx[MAXF];             // fact index, same order
__device__ int2     g_matchF[MAXSTATES * KF]; // (fact_idx, packed key)
__device__ int      g_matchR[MAXSTATES * KR];
__device__ int      g_nf[MAXSTATES];
__device__ int      g_nr[MAXSTATES];
__device__ int      g_batchCnt[MAXB];

// ---------------- K1: histogram, 4 chunks per block (MLP=4) ----------------
__global__ __launch_bounds__(SORT_BLK, 2) void k_hist(const int* __restrict__ facts, int F, int nB) {
    __shared__ int warpHist[HCH][SNW][NPREDS];
    int t = threadIdx.x, w = t >> 5, lane = t & 31;
    if (blockIdx.x == 0 && t < MAXB) g_batchCnt[t] = 0;   // reset epilogue counters
    for (int j = t; j < HCH * SNW * NPREDS; j += SORT_BLK)
        ((int*)warpHist)[j] = 0;
    __syncthreads();

    int p[HCH];
    #pragma unroll
    for (int c = 0; c < HCH; c++) {           // issue all loads first (MLP)
        int i = (blockIdx.x * HCH + c) * SORT_BLK + t;
        p[c] = (i < F) ? __ldg(&facts[3 * i]) : -1;
        if (p[c] < 0 || p[c] >= NPREDS) p[c] = -1;
    }
    #pragma unroll
    for (int c = 0; c < HCH; c++) {
        unsigned mask = __match_any_sync(0xffffffffu, p[c]);
        if (p[c] >= 0 && lane == (__ffs(mask) - 1)) warpHist[c][w][p[c]] = __popc(mask);
    }
    __syncthreads();
    if (t < NPREDS) {
        #pragma unroll
        for (int c = 0; c < HCH; c++) {
            int chunk = blockIdx.x * HCH + c;
            if (chunk < nB) {
                int run = 0;
                #pragma unroll
                for (int ww = 0; ww < SNW; ww++) run += warpHist[c][ww][t];
                g_hist[t * nB + chunk] = run;
            }
        }
    }
}

// ---------------- K2: stable scatter, 2 chunks per block ----------------
__global__ __launch_bounds__(SORT_BLK, 2) void k_scatter(const int* __restrict__ facts, int F, int nB) {
    __shared__ int warpHist[SCH][SNW][NPREDS];  // counts -> exclusive prefixes across warps
    __shared__ int predOff[SCH][NPREDS];        // per-chunk base within each bucket
    __shared__ int predTot[NPREDS];             // per-pred global totals
    __shared__ int sStart[NPREDS];              // bucket starts
    int t = threadIdx.x, w = t >> 5, lane = t & 31;
    int chunk0 = blockIdx.x * SCH;

    for (int j = t; j < SCH * SNW * NPREDS; j += SORT_BLK)
        ((int*)warpHist)[j] = 0;
    __syncthreads();

    int p[SCH], a0[SCH], a1[SCH], rank[SCH];
    #pragma unroll
    for (int c = 0; c < SCH; c++) {
        int i = (chunk0 + c) * SORT_BLK + t;
        if (i < F) {
            p[c]  = facts[3 * i];
            a0[c] = facts[3 * i + 1];
            a1[c] = facts[3 * i + 2];
            if (p[c] < 0 || p[c] >= NPREDS) p[c] = -1;
        } else p[c] = -1, a0[c] = 0, a1[c] = 0;
    }
    #pragma unroll
    for (int c = 0; c < SCH; c++) {
        unsigned mask = __match_any_sync(0xffffffffu, p[c]);
        rank[c] = __popc(mask & ((1u << lane) - 1));
        if (p[c] >= 0 && lane == (__ffs(mask) - 1)) warpHist[c][w][p[c]] = __popc(mask);
    }
    __syncthreads();

    // warp-per-pred: one masked-sum pass over the global hist serves both chunks
    #pragma unroll
    for (int rep = 0; rep < 2; rep++) {
        int pred = w + rep * SNW;
        if (pred < NPREDS) {
            int before = 0, total = 0;
            for (int base = 0; base < nB; base += 32) {
                int j = base + lane;
                int v = (j < nB) ? __ldg(&g_hist[pred * nB + j]) : 0;
                total += v;
                if (j < chunk0) before += v;
            }
            #pragma unroll
            for (int o = 16; o; o >>= 1) {
                before += __shfl_down_sync(0xffffffffu, before, o);
                total  += __shfl_down_sync(0xffffffffu, total, o);
            }
            if (lane == 0) { predOff[0][pred] = before; predTot[pred] = total; }
        }
    }
    // t<52: exclusive scans of warpHist across warps per chunk; keep chunk-0 local total
    int localTot0 = 0;
    if (t < NPREDS) {
        #pragma unroll
        for (int c = 0; c < SCH; c++) {
            int run = 0;
            #pragma unroll
            for (int ww = 0; ww < SNW; ww++) {
                int v = warpHist[c][ww][t];
                warpHist[c][ww][t] = run;
                run += v;
            }
            if (c == 0) localTot0 = run;
        }
    }
    __syncthreads();
    if (t < NPREDS) predOff[1][t] = predOff[0][t] + localTot0;
    // warp 0: exclusive scan of 52 bucket totals -> starts
    if (w == 0) {
        int cA = (lane < NPREDS) ? predTot[lane] : 0;
        int cB = (32 + lane < NPREDS) ? predTot[32 + lane] : 0;
        int incA = cA;
        #pragma unroll
        for (int o = 1; o < 32; o <<= 1) {
            int n = __shfl_up_sync(0xffffffffu, incA, o);
            if (lane >= o) incA += n;
        }
        int baseB = __shfl_sync(0xffffffffu, incA, 31);
        int incB = cB;
        #pragma unroll
        for (int o = 1; o < 32; o <<= 1) {
            int n = __shfl_up_sync(0xffffffffu, incB, o);
            if (lane >= o) incB += n;
        }
        if (lane < NPREDS) sStart[lane] = incA - cA;
        if (32 + lane < NPREDS) sStart[32 + lane] = baseB + incB - cB;
    }
    __syncthreads();
    if (blockIdx.x == 0 && t < NPREDS) {   // publish for k_match
        g_bucketCount[t] = predTot[t];
        g_bucketStart[t] = sStart[t];
    }

    #pragma unroll
    for (int c = 0; c < SCH; c++) {
        if (p[c] >= 0) {
            int pos = sStart[p[c]] + predOff[c][p[c]] + warpHist[c][w][p[c]] + rank[c];
            g_keys[pos] = (unsigned)a0[c] | ((unsigned)a1[c] << 14);
            g_sIdx[pos] = (chunk0 + c) * SORT_BLK + t;
        }
    }
}

// ---------------- K3: per-state match + fused last-block select epilogue ----------------
__global__ __launch_bounds__(MT) void k_match(const int* __restrict__ goals,
                                              const float* __restrict__ stateScores,
                                              const float* __restrict__ factScores,
                                              const int* __restrict__ heads,
                                              const int* __restrict__ bodies,
                                              const int* __restrict__ ruleLens,
                                              const float* __restrict__ ruleScores,
                                              float* __restrict__ out,
                                              int R, int numStates) {
    int state = blockIdx.x;
    int batch = state / SS;
    const int* pg = goals + state * GG * 3;
    int qp = pg[0], qa0 = pg[1], qa1 = pg[2];
    int t = threadIdx.x, w = t >> 5, lane = t & 31;
    unsigned lmask = (1u << lane) - 1;

    __shared__ int2 buf[MNW][KF];
    __shared__ int warpCnt[MNW];
    __shared__ int prefixW[MNW];
    __shared__ int totalSh;

    int nf = 0, nr = 0;
    bool active = (qp > 0) && (qp < NPREDS);
    if (active) {
        bool v0 = qa0 > CONST_NO, v1 = qa1 > CONST_NO;
        int start = __ldg(&g_bucketStart[qp]);
        int cnt = __ldg(&g_bucketCount[qp]);

        if (v0 && v1) {
            nf = min(cnt, KF);
            if (t < nf)
                g_matchF[state * KF + t] =
                    make_int2(__ldg(&g_sIdx[start + t]), (int)__ldg(&g_keys[start + t]));
        } else {
            unsigned target = (v0 ? 0u : (unsigned)qa0) | ((v1 ? 0u : (unsigned)qa1) << 14);
            unsigned kmask  = (v0 ? 0u : 0x3FFFu)       | ((v1 ? 0u : (0x3FFFu << 14)));

            int seg = (cnt + MNW - 1) / MNW;
            int s0 = w * seg;
            int s1 = min(s0 + seg, cnt);
            int myCnt = 0;
            for (int base = s0; base < s1; base += 128) {
                unsigned k[4];
                bool m[4];
                #pragma unroll
                for (int u = 0; u < 4; u++) {
                    int i = base + u * 32 + lane;
                    k[u] = (i < s1) ? __ldg(&g_keys[start + i]) : 0xFFFFFFFFu;
                }
                #pragma unroll
                for (int u = 0; u < 4; u++) {
                    int i = base + u * 32 + lane;
                    m[u] = (i < s1) && ((k[u] & kmask) == target);
                }
                #pragma unroll
                for (int u = 0; u < 4; u++) {
                    unsigned bal = __ballot_sync(0xffffffffu, m[u]);
                    int pos = myCnt + __popc(bal & lmask);
                    if (m[u] && pos < KF)
                        buf[w][pos] = make_int2(__ldg(&g_sIdx[start + base + u * 32 + lane]),
                                                (int)k[u]);
                    myCnt += __popc(bal);
                }
                if (myCnt >= KF) break;
            }
            myCnt = min(myCnt, KF);
            if (lane == 0) warpCnt[w] = myCnt;
            __syncthreads();
            if (w == 0) {
                int c = (lane < MNW) ? warpCnt[lane] : 0;
                int inc = c;
                #pragma unroll
                for (int o = 1; o < 32; o <<= 1) {
                    int n = __shfl_up_sync(0xffffffffu, inc, o);
                    if (lane >= o) inc += n;
                }
                if (lane < MNW) prefixW[lane] = inc - c;
                if (lane == MNW - 1) totalSh = inc;
            }
            __syncthreads();
            nf = min(totalSh, KF);
            {
                int off = prefixW[w];
                int cntW = warpCnt[w];
                for (int j = lane; j < cntW; j += 32) {
                    int gpos = off + j;
                    if (gpos < KF) g_matchF[state * KF + gpos] = buf[w][j];
                }
            }
            __syncthreads();
        }

        // ---- rules ----
        int segR = (R + MNW - 1) / MNW;
        int r0 = w * segR;
        int r1 = min(r0 + segR, R);
        int myCnt = 0;
        for (int base = r0; base < r1; base += 32) {
            int i = base + lane;
            bool m = false;
            if (i < r1) {
                int hp = __ldg(&heads[3 * i]);
                int h1 = __ldg(&heads[3 * i + 1]);
                int h2 = __ldg(&heads[3 * i + 2]);
                m = (hp == qp)
                    && (h1 > CONST_NO || v0 || qa0 == h1)
                    && (h2 > CONST_NO || v1 || qa1 == h2);
            }
            unsigned bal = __ballot_sync(0xffffffffu, m);
            int pos = myCnt + __popc(bal & lmask);
            if (m && pos < KR) buf[w][pos].x = i;
            myCnt += __popc(bal);
            if (myCnt >= KR) break;
        }
        myCnt = min(myCnt, KR);
        if (lane == 0) warpCnt[w] = myCnt;
        __syncthreads();
        if (w == 0) {
            int c = (lane < MNW) ? warpCnt[lane] : 0;
            int inc = c;
            #pragma unroll
            for (int o = 1; o < 32; o <<= 1) {
                int n = __shfl_up_sync(0xffffffffu, inc, o);
                if (lane >= o) inc += n;
            }
            if (lane < MNW) prefixW[lane] = inc - c;
            if (lane == MNW - 1) totalSh = inc;
        }
        __syncthreads();
        nr = min(totalSh, KR);
        {
            int off = prefixW[w];
            int cntW = warpCnt[w];
            for (int j = lane; j < cntW; j += 32) {
                int gpos = off + j;
                if (gpos < KR) g_matchR[state * KR + gpos] = buf[w][j].x;
            }
        }
    }
    if (t == 0) {
        g_nf[state] = nf;
        g_nr[state] = nr;
    }

    // ================= fused epilogue: last block of the batch does select =================
    __shared__ bool isLast;
    __syncthreads();
    if (t == 0) {
        __threadfence();
        int v = atomicAdd(&g_batchCnt[batch], 1);
        isLast = (v == SS - 1);
    }
    __syncthreads();
    if (!isLast) return;
    __threadfence();

    __shared__ int cum[SS + 1];
    __shared__ int snf[SS];
    if (t < SS) {
        int nfs = g_nf[batch * SS + t];
        int c = nfs + g_nr[batch * SS + t];
        snf[t] = nfs;
        int sl = t & 31;
        int inc = c;
        #pragma unroll
        for (int o = 1; o < 32; o <<= 1) {
            int n = __shfl_up_sync(0xffffffffu, inc, o);
            if (sl >= o) inc += n;
        }
        cum[t + 1] = inc;
        if (t == 0) cum[0] = 0;
    }
    __syncthreads();
    if (t == 0) {
        int base = cum[32];
        #pragma unroll
        for (int s = 33; s <= SS; s++) cum[s] += base;
    }
    __syncthreads();

    int goalsCount = numStates * GG * 3;
    int j = t >> 3;          // output slot (64 slots x 8 threads)
    int sub = t & 7;         // elements sub*3 .. sub*3+2
    int outBase = (batch * SS + j) * (GG * 3);
    int total = cum[SS];

    if (j < total) {
        int s = 0;
        #pragma unroll
        for (int step = 32; step; step >>= 1)
            if (s + step <= SS && cum[s + step] <= j) s += step;
        int off = j - cum[s];
        int st = batch * SS + s;
        int nfs = snf[s];
        const int* pgs = goals + st * GG * 3;
        int ga0 = __ldg(&pgs[1]), ga1 = __ldg(&pgs[2]);
        float ss = __ldg(&stateScores[st]);
        float score;
        if (off < nfs) {
            int2 mk = g_matchF[st * KF + off];
            int fi = mk.x;
            int b0 = mk.y & 0x3FFF, b1 = (mk.y >> 14) & 0x3FFF;
            bool v0 = ga0 > CONST_NO, v1 = ga1 > CONST_NO;
            #pragma unroll
            for (int u = 0; u < 3; u++) {
                int e = sub * 3 + u;
                int x = (e < 3) ? PADV : __ldg(&pgs[e]);
                if (v0 && x == ga0) x = b0;
                if (v1 && x == ga1) x = b1;
                out[outBase + e] = (float)x;
            }
            score = ss * __ldg(&factScores[fi]);
        } else {
            int ri = g_matchR[st * KR + (off - nfs)];
            int h1 = __ldg(&heads[3 * ri + 1]), h2 = __ldg(&heads[3 * ri + 2]);
            bool v0 = h1 > CONST_NO, v1 = h2 > CONST_NO;
            int len = __ldg(&ruleLens[ri]);
            #pragma unroll
            for (int u = 0; u < 3; u++) {
                int e = sub * 3 + u;
                int jg = e / 3;
                int x;
                if (jg < 3) {
                    x = __ldg(&bodies[ri * 9 + e]);
                    if (v0 && x == h1) x = ga0;
                    if (v1 && x == h2) x = ga1;
                    if (jg >= len) x = PADV;
                } else {
                    x = __ldg(&pgs[e - 6]);   // (jg-2)*3 + c == e - 6
                }
                out[outBase + e] = (float)x;
            }
            score = ss * __ldg(&ruleScores[ri]);
        }
        if (sub == 0) out[goalsCount + batch * SS + j] = score;
    } else {
        #pragma unroll
        for (int u = 0; u < 3; u++)
            out[outBase + sub * 3 + u] = 0.0f;
        if (sub == 0) out[goalsCount + batch * SS + j] = 0.0f;
    }
}

extern "C" void kernel_launch(void* const* d_in, const int* in_sizes, int n_in,
                              void* d_out, int out_size) {
    const int* goals = (const int*)d_in[0];            // (B,S,G,3) int32
    const float* stateScores = (const float*)d_in[1];  // (B,S)
    const int* facts = (const int*)d_in[2];            // (F,3)
    const float* factScores = (const float*)d_in[3];
    const int* heads = (const int*)d_in[4];            // (R,3)
    const int* bodies = (const int*)d_in[5];           // (R,3,3)
    const int* ruleLens = (const int*)d_in[6];
    const float* ruleScores = (const float*)d_in[7];

    int F = in_sizes[2] / 3;
    int R = in_sizes[4] / 3;
    int numStates = in_sizes[1];       // B*S
    int nB = (F + SORT_BLK - 1) / SORT_BLK;

    int gridH = (nB + HCH - 1) / HCH;
    int gridS = (nB + SCH - 1) / SCH;
    k_hist<<<gridH, SORT_BLK>>>(facts, F, nB);
    k_scatter<<<gridS, SORT_BLK>>>(facts, F, nB);
    k_match<<<numStates, MT>>>(goals, stateScores, factScores, heads, bodies,
                               ruleLens, ruleScores, (float*)d_out, R, numStates);
}

// round 14
// speedup vs baseline: 1.1951x; 1.1951x over previous
#include <cuda_runtime.h>

#define CONST_NO 10000
#define PADV 0

constexpr int GG = 8;      // goals per state
constexpr int SS = 64;     // states per batch
constexpr int KF = 64;     // fact top-k
constexpr int KR = 32;     // rule top-k
constexpr int MAXSTATES = 512;
constexpr int MAXB = MAXSTATES / SS;
constexpr int NPREDS = 52;      // predicate ids 1..50 (+pad margin)
constexpr int SORT_BLK = 1024;
constexpr int SNW = SORT_BLK / 32;  // 32 warps
constexpr int NBLK = 148;           // exactly one wave on GB300
constexpr int MAXF = 200704;
constexpr int MT = 512;         // match threads per block
constexpr int MNW = MT / 32;    // match warps per block (16)

__device__ int      g_hist[NPREDS * NBLK];    // [pred][block] totals
__device__ int      g_bucketCount[NPREDS];
__device__ int      g_bucketStart[NPREDS];
__device__ unsigned g_keys[MAXF];             // packed (a0 | a1<<14), bucketed, index-ordered
__device__ int      g_sIdx[MAXF];             // fact index, same order
__device__ int2     g_matchF[MAXSTATES * KF]; // (fact_idx, packed key)
__device__ int      g_matchR[MAXSTATES * KR];
__device__ int      g_nf[MAXSTATES];
__device__ int      g_nr[MAXSTATES];
__device__ int      g_batchCnt[MAXB];

// ---------------- K1: per-block totals histogram (grid = 148, one wave) ----------------
__global__ __launch_bounds__(SORT_BLK, 2) void k_hist(const int* __restrict__ facts, int F, int per) {
    __shared__ int warpHist[SNW][NPREDS];
    int t = threadIdx.x, w = t >> 5, lane = t & 31;
    if (blockIdx.x == 0 && t < MAXB) g_batchCnt[t] = 0;   // reset epilogue counters
    for (int j = t; j < SNW * NPREDS; j += SORT_BLK)
        ((int*)warpHist)[j] = 0;
    __syncthreads();
    int start = blockIdx.x * per;
    int end = min(start + per, F);
    for (int i0 = start; i0 < end; i0 += SORT_BLK) {
        int i = i0 + t;
        int p = (i < end) ? __ldg(&facts[3 * i]) : -1;
        if (p < 0 || p >= NPREDS) p = -1;
        unsigned mask = __match_any_sync(0xffffffffu, p);
        if (p >= 0 && lane == (__ffs(mask) - 1)) warpHist[w][p] += __popc(mask);
    }
    __syncthreads();
    if (t < NPREDS) {
        int run = 0;
        #pragma unroll
        for (int ww = 0; ww < SNW; ww++) run += warpHist[ww][t];
        g_hist[t * NBLK + blockIdx.x] = run;
    }
}

// ---------------- K2: stable scatter (grid = 148, one wave) ----------------
__global__ __launch_bounds__(SORT_BLK, 2) void k_scatter(const int* __restrict__ facts, int F, int per) {
    __shared__ int warpHist[SNW][NPREDS];   // per-iteration counts -> exclusive prefixes
    __shared__ int blockBase[NPREDS];       // this block's base within each bucket
    __shared__ int runLocal[NPREDS];        // facts of pred p already emitted by this block
    __shared__ int predTot[NPREDS];         // global totals per pred
    __shared__ int sStart[NPREDS];          // bucket starts
    int t = threadIdx.x, w = t >> 5, lane = t & 31;
    int myB = blockIdx.x;

    // one-time: warp-per-pred masked sums over the 148-entry hist rows
    #pragma unroll
    for (int rep = 0; rep < 2; rep++) {
        int pred = w + rep * SNW;
        if (pred < NPREDS) {
            int before = 0, total = 0;
            #pragma unroll
            for (int base = 0; base < NBLK; base += 32) {
                int j = base + lane;
                int v = (j < NBLK) ? __ldg(&g_hist[pred * NBLK + j]) : 0;
                total += v;
                if (j < myB) before += v;
            }
            #pragma unroll
            for (int o = 16; o; o >>= 1) {
                before += __shfl_down_sync(0xffffffffu, before, o);
                total  += __shfl_down_sync(0xffffffffu, total, o);
            }
            if (lane == 0) { blockBase[pred] = before; predTot[pred] = total; }
        }
    }
    if (t < NPREDS) runLocal[t] = 0;
    __syncthreads();
    // warp 0: exclusive scan of 52 bucket totals -> starts
    if (w == 0) {
        int cA = (lane < NPREDS) ? predTot[lane] : 0;
        int cB = (32 + lane < NPREDS) ? predTot[32 + lane] : 0;
        int incA = cA;
        #pragma unroll
        for (int o = 1; o < 32; o <<= 1) {
            int n = __shfl_up_sync(0xffffffffu, incA, o);
            if (lane >= o) incA += n;
        }
        int baseB = __shfl_sync(0xffffffffu, incA, 31);
        int incB = cB;
        #pragma unroll
        for (int o = 1; o < 32; o <<= 1) {
            int n = __shfl_up_sync(0xffffffffu, incB, o);
            if (lane >= o) incB += n;
        }
        if (lane < NPREDS) sStart[lane] = incA - cA;
        if (32 + lane < NPREDS) sStart[32 + lane] = baseB + incB - cB;
    }
    __syncthreads();
    if (myB == 0 && t < NPREDS) {   // publish for k_match
        g_bucketCount[t] = predTot[t];
        g_bucketStart[t] = sStart[t];
    }

    int start = myB * per;
    int end = min(start + per, F);
    for (int i0 = start; i0 < end; i0 += SORT_BLK) {
        // zero per-iter warp hist
        for (int j = t; j < SNW * NPREDS; j += SORT_BLK)
            ((int*)warpHist)[j] = 0;
        __syncthreads();
        int i = i0 + t;
        int p = -1, a0 = 0, a1 = 0;
        if (i < end) {
            p  = facts[3 * i];
            a0 = facts[3 * i + 1];
            a1 = facts[3 * i + 2];
            if (p < 0 || p >= NPREDS) p = -1;
        }
        unsigned mask = __match_any_sync(0xffffffffu, p);
        int rank = __popc(mask & ((1u << lane) - 1));
        if (p >= 0 && lane == (__ffs(mask) - 1)) warpHist[w][p] = __popc(mask);
        __syncthreads();
        int iterTot = 0;
        if (t < NPREDS) {
            int run = 0;
            #pragma unroll
            for (int ww = 0; ww < SNW; ww++) {
                int v = warpHist[ww][t];
                warpHist[ww][t] = run;
                run += v;
            }
            iterTot = run;
        }
        __syncthreads();
        if (p >= 0) {
            int pos = sStart[p] + blockBase[p] + runLocal[p] + warpHist[w][p] + rank;
            g_keys[pos] = (unsigned)a0 | ((unsigned)a1 << 14);
            g_sIdx[pos] = i;
        }
        __syncthreads();
        if (t < NPREDS) runLocal[t] += iterTot;
    }
}

// ---------------- K3: per-state match + fused last-block select epilogue ----------------
__global__ __launch_bounds__(MT) void k_match(const int* __restrict__ goals,
                                              const float* __restrict__ stateScores,
                                              const float* __restrict__ factScores,
                                              const int* __restrict__ heads,
                                              const int* __restrict__ bodies,
                                              const int* __restrict__ ruleLens,
                                              const float* __restrict__ ruleScores,
                                              float* __restrict__ out,
                                              int R, int numStates) {
    int state = blockIdx.x;
    int batch = state / SS;
    const int* pg = goals + state * GG * 3;
    int qp = pg[0], qa0 = pg[1], qa1 = pg[2];
    int t = threadIdx.x, w = t >> 5, lane = t & 31;
    unsigned lmask = (1u << lane) - 1;

    __shared__ int2 buf[MNW][KF];
    __shared__ int warpCnt[MNW];
    __shared__ int prefixW[MNW];
    __shared__ int totalSh;

    int nf = 0, nr = 0;
    bool active = (qp > 0) && (qp < NPREDS);
    if (active) {
        bool v0 = qa0 > CONST_NO, v1 = qa1 > CONST_NO;
        int start = __ldg(&g_bucketStart[qp]);
        int cnt = __ldg(&g_bucketCount[qp]);

        if (v0 && v1) {
            nf = min(cnt, KF);
            if (t < nf)
                g_matchF[state * KF + t] =
                    make_int2(__ldg(&g_sIdx[start + t]), (int)__ldg(&g_keys[start + t]));
        } else {
            unsigned target = (v0 ? 0u : (unsigned)qa0) | ((v1 ? 0u : (unsigned)qa1) << 14);
            unsigned kmask  = (v0 ? 0u : 0x3FFFu)       | ((v1 ? 0u : (0x3FFFu << 14)));

            int seg = (cnt + MNW - 1) / MNW;
            int s0 = w * seg;
            int s1 = min(s0 + seg, cnt);
            int myCnt = 0;
            for (int base = s0; base < s1; base += 128) {
                unsigned k[4];
                bool m[4];
                #pragma unroll
                for (int u = 0; u < 4; u++) {
                    int i = base + u * 32 + lane;
                    k[u] = (i < s1) ? __ldg(&g_keys[start + i]) : 0xFFFFFFFFu;
                }
                #pragma unroll
                for (int u = 0; u < 4; u++) {
                    int i = base + u * 32 + lane;
                    m[u] = (i < s1) && ((k[u] & kmask) == target);
                }
                #pragma unroll
                for (int u = 0; u < 4; u++) {
                    unsigned bal = __ballot_sync(0xffffffffu, m[u]);
                    int pos = myCnt + __popc(bal & lmask);
                    if (m[u] && pos < KF)
                        buf[w][pos] = make_int2(__ldg(&g_sIdx[start + base + u * 32 + lane]),
                                                (int)k[u]);
                    myCnt += __popc(bal);
                }
                if (myCnt >= KF) break;
            }
            myCnt = min(myCnt, KF);
            if (lane == 0) warpCnt[w] = myCnt;
            __syncthreads();
            if (w == 0) {
                int c = (lane < MNW) ? warpCnt[lane] : 0;
                int inc = c;
                #pragma unroll
                for (int o = 1; o < 32; o <<= 1) {
                    int n = __shfl_up_sync(0xffffffffu, inc, o);
                    if (lane >= o) inc += n;
                }
                if (lane < MNW) prefixW[lane] = inc - c;
                if (lane == MNW - 1) totalSh = inc;
            }
            __syncthreads();
            nf = min(totalSh, KF);
            {
                int off = prefixW[w];
                int cntW = warpCnt[w];
                for (int j = lane; j < cntW; j += 32) {
                    int gpos = off + j;
                    if (gpos < KF) g_matchF[state * KF + gpos] = buf[w][j];
                }
            }
            __syncthreads();
        }

        // ---- rules ----
        int segR = (R + MNW - 1) / MNW;
        int r0 = w * segR;
        int r1 = min(r0 + segR, R);
        int myCnt = 0;
        for (int base = r0; base < r1; base += 32) {
            int i = base + lane;
            bool m = false;
            if (i < r1) {
                int hp = __ldg(&heads[3 * i]);
                int h1 = __ldg(&heads[3 * i + 1]);
                int h2 = __ldg(&heads[3 * i + 2]);
                m = (hp == qp)
                    && (h1 > CONST_NO || v0 || qa0 == h1)
                    && (h2 > CONST_NO || v1 || qa1 == h2);
            }
            unsigned bal = __ballot_sync(0xffffffffu, m);
            int pos = myCnt + __popc(bal & lmask);
            if (m && pos < KR) buf[w][pos].x = i;
            myCnt += __popc(bal);
            if (myCnt >= KR) break;
        }
        myCnt = min(myCnt, KR);
        if (lane == 0) warpCnt[w] = myCnt;
        __syncthreads();
        if (w == 0) {
            int c = (lane < MNW) ? warpCnt[lane] : 0;
            int inc = c;
            #pragma unroll
            for (int o = 1; o < 32; o <<= 1) {
                int n = __shfl_up_sync(0xffffffffu, inc, o);
                if (lane >= o) inc += n;
            }
            if (lane < MNW) prefixW[lane] = inc - c;
            if (lane == MNW - 1) totalSh = inc;
        }
        __syncthreads();
        nr = min(totalSh, KR);
        {
            int off = prefixW[w];
            int cntW = warpCnt[w];
            for (int j = lane; j < cntW; j += 32) {
                int gpos = off + j;
                if (gpos < KR) g_matchR[state * KR + gpos] = buf[w][j].x;
            }
        }
    }
    if (t == 0) {
        g_nf[state] = nf;
        g_nr[state] = nr;
    }

    // ================= fused epilogue: last block of the batch does select =================
    __shared__ bool isLast;
    __syncthreads();
    if (t == 0) {
        __threadfence();
        int v = atomicAdd(&g_batchCnt[batch], 1);
        isLast = (v == SS - 1);
    }
    __syncthreads();
    if (!isLast) return;
    __threadfence();

    __shared__ int cum[SS + 1];
    __shared__ int snf[SS];
    if (t < SS) {
        int nfs = g_nf[batch * SS + t];
        int c = nfs + g_nr[batch * SS + t];
        snf[t] = nfs;
        int sl = t & 31;
        int inc = c;
        #pragma unroll
        for (int o = 1; o < 32; o <<= 1) {
            int n = __shfl_up_sync(0xffffffffu, inc, o);
            if (sl >= o) inc += n;
        }
        cum[t + 1] = inc;
        if (t == 0) cum[0] = 0;
    }
    __syncthreads();
    if (t == 0) {
        int base = cum[32];
        #pragma unroll
        for (int s = 33; s <= SS; s++) cum[s] += base;
    }
    __syncthreads();

    int goalsCount = numStates * GG * 3;
    int j = t >> 3;          // output slot (64 slots x 8 threads)
    int sub = t & 7;         // elements sub*3 .. sub*3+2
    int outBase = (batch * SS + j) * (GG * 3);
    int total = cum[SS];

    if (j < total) {
        int s = 0;
        #pragma unroll
        for (int step = 32; step; step >>= 1)
            if (s + step <= SS && cum[s + step] <= j) s += step;
        int off = j - cum[s];
        int st = batch * SS + s;
        int nfs = snf[s];
        const int* pgs = goals + st * GG * 3;
        int ga0 = __ldg(&pgs[1]), ga1 = __ldg(&pgs[2]);
        float ss = __ldg(&stateScores[st]);
        float score;
        if (off < nfs) {
            int2 mk = g_matchF[st * KF + off];
            int fi = mk.x;
            int b0 = mk.y & 0x3FFF, b1 = (mk.y >> 14) & 0x3FFF;
            bool v0 = ga0 > CONST_NO, v1 = ga1 > CONST_NO;
            #pragma unroll
            for (int u = 0; u < 3; u++) {
                int e = sub * 3 + u;
                int x = (e < 3) ? PADV : __ldg(&pgs[e]);
                if (v0 && x == ga0) x = b0;
                if (v1 && x == ga1) x = b1;
                out[outBase + e] = (float)x;
            }
            score = ss * __ldg(&factScores[fi]);
        } else {
            int ri = g_matchR[st * KR + (off - nfs)];
            int h1 = __ldg(&heads[3 * ri + 1]), h2 = __ldg(&heads[3 * ri + 2]);
            bool v0 = h1 > CONST_NO, v1 = h2 > CONST_NO;
            int len = __ldg(&ruleLens[ri]);
            #pragma unroll
            for (int u = 0; u < 3; u++) {
                int e = sub * 3 + u;
                int jg = e / 3;
                int x;
                if (jg < 3) {
                    x = __ldg(&bodies[ri * 9 + e]);
                    if (v0 && x == h1) x = ga0;
                    if (v1 && x == h2) x = ga1;
                    if (jg >= len) x = PADV;
                } else {
                    x = __ldg(&pgs[e - 6]);   // (jg-2)*3 + c == e - 6
                }
                out[outBase + e] = (float)x;
            }
            score = ss * __ldg(&ruleScores[ri]);
        }
        if (sub == 0) out[goalsCount + batch * SS + j] = score;
    } else {
        #pragma unroll
        for (int u = 0; u < 3; u++)
            out[outBase + sub * 3 + u] = 0.0f;
        if (sub == 0) out[goalsCount + batch * SS + j] = 0.0f;
    }
}

extern "C" void kernel_launch(void* const* d_in, const int* in_sizes, int n_in,
                              void* d_out, int out_size) {
    const int* goals = (const int*)d_in[0];            // (B,S,G,3) int32
    const float* stateScores = (const float*)d_in[1];  // (B,S)
    const int* facts = (const int*)d_in[2];            // (F,3)
    const float* factScores = (const float*)d_in[3];
    const int* heads = (const int*)d_in[4];            // (R,3)
    const int* bodies = (const int*)d_in[5];           // (R,3,3)
    const int* ruleLens = (const int*)d_in[6];
    const float* ruleScores = (const float*)d_in[7];

    int F = in_sizes[2] / 3;
    int R = in_sizes[4] / 3;
    int numStates = in_sizes[1];       // B*S
    int per = (F + NBLK - 1) / NBLK;   // contiguous facts per block

    k_hist<<<NBLK, SORT_BLK>>>(facts, F, per);
    k_scatter<<<NBLK, SORT_BLK>>>(facts, F, per);
    k_match<<<numStates, MT>>>(goals, stateScores, factScores, heads, bodies,
                               ruleLens, ruleScores, (float*)d_out, R, numStates);
}